// round 8
// baseline (speedup 1.0000x reference)
#include <cuda_runtime.h>

#define WI 512
#define HI 512
#define BN 8
#define CN 8
#define HW (HI * WI)
#define TPB 128
#define PXT 4
#define NTHREADS (BN * HW / PXT)   // 524288
#define NBLK (NTHREADS / TPB)      // 4096

// Accumulators (module-load zeroed; last block resets for graph replay).
__device__ double g_big;
__device__ double g_small;
__device__ unsigned g_ticket;

__device__ __forceinline__ float sigf(float x) {
    return __fdividef(1.0f, 1.0f + __expf(-x));   // EX2 + RCP
}
#define CLOG2_MIN (-144.26950408889634f)          // -100 / ln2
__device__ __forceinline__ float clog2f_(float x) {
    return fmaxf(__log2f(x), CLOG2_MIN);
}
__device__ __forceinline__ float4 ld4(const float* p) {
    return __ldg((const float4*)p);
}
__device__ __forceinline__ float4 sig4(float4 x) {
    return make_float4(sigf(x.x), sigf(x.y), sigf(x.z), sigf(x.w));
}

// Neighbor probs for 4 pixels from row base (plane row r+dr), shift dw.
// OOB (row or column) -> prob 0 exactly (shifts zero-pad the probability).
__device__ __forceinline__ float4 nbr4(const float* row, bool rv, int w0, int dw) {
    if (!rv) return make_float4(0.f, 0.f, 0.f, 0.f);
    float4 f = ld4(row + w0);
    if (dw == 0) return sig4(f);
    if (dw < 0) {
        float e = (w0 > 0) ? sigf(__ldg(row + w0 - 1)) : 0.f;
        return make_float4(e, sigf(f.x), sigf(f.y), sigf(f.z));
    }
    float e = (w0 + 4 < WI) ? sigf(__ldg(row + w0 + 4)) : 0.f;
    return make_float4(sigf(f.y), sigf(f.z), sigf(f.w), e);
}

struct Acc { float prodP, prodV, extra, g1, g2, s, vmin; };

__device__ __forceinline__ void lane_acc(float pa, float pd, float n1, float n2,
                                         float t, Acc& a) {
    float v1 = pa * n1, v2 = pd * n2;
    bool tt = t > 0.5f;                    // binary target
    float fa = tt ? pa : 1.f - pa;
    float fd = tt ? pd : 1.f - pd;
    a.prodP *= fa * fd;
    float f1 = tt ? v1 : 1.f - v1;
    float f2 = tt ? v2 : 1.f - v2;
    // f1 == 0 only at zero-padded borders with t==1, and then f2 == 0 too
    // (same padding geometry): both clamp to -100, weight 0.2 each -> -40.
    if (f1 == 0.f) a.extra += -40.f;
    else           a.prodV *= f1 * f2;
    a.g1 += v1; a.g2 += v2; a.s += t;
    a.vmin = fminf(a.vmin, v2);
}

#define LACC4(pa4, pd4, n1, n2, t4)                          \
    do {                                                     \
        lane_acc(pa4.x, pd4.x, n1.x, n2.x, t4.x, ac[0]);     \
        lane_acc(pa4.y, pd4.y, n1.y, n2.y, t4.y, ac[1]);     \
        lane_acc(pa4.z, pd4.z, n1.z, n2.z, t4.z, ac[2]);     \
        lane_acc(pa4.w, pd4.w, n1.w, n2.w, t4.w, ac[3]);     \
    } while (0)

__global__ void __launch_bounds__(TPB) loss_k(
    const float* __restrict__ atts, const float* __restrict__ dets,
    const float* __restrict__ target, const float* __restrict__ con,
    float* __restrict__ out)
{
    int idx = blockIdx.x * TPB + threadIdx.x;       // [0, NTHREADS)
    int w0 = (idx & (WI / 4 - 1)) * 4;              // 128 float4 groups per row
    int r  = (idx >> 7) & (HI - 1);
    int b  = idx >> 16;
    int off = r * WI + w0;

    const float* A = atts + (size_t)b * CN * HW;
    const float* D = dets + (size_t)b * CN * HW;
    const float* C = con  + (size_t)b * CN * HW;

    Acc ac[4];
#pragma unroll
    for (int i = 0; i < 4; i++) ac[i] = {1.f, 1.f, 0.f, 0.f, 0.f, 0.f, 2.f};

    // Stash planes 3 & 4 centers: they double as same-row neighbors.
    float4 pa3 = sig4(ld4(A + 3 * HW + off));
    float4 pd3 = sig4(ld4(D + 3 * HW + off));
    float4 pa4 = sig4(ld4(A + 4 * HW + off));
    float4 pd4 = sig4(ld4(D + 4 * HW + off));

    {   // ch=3: neighbor plane 4 at (r, w-1) -> shift stashed centers right
        float eA = (w0 > 0) ? sigf(__ldg(A + 4 * HW + off - 1)) : 0.f;
        float eD = (w0 > 0) ? sigf(__ldg(D + 4 * HW + off - 1)) : 0.f;
        float4 n1 = make_float4(eA, pa4.x, pa4.y, pa4.z);
        float4 n2 = make_float4(eD, pd4.x, pd4.y, pd4.z);
        float4 t4 = ld4(C + 3 * HW + off);
        LACC4(pa3, pd3, n1, n2, t4);
    }
    {   // ch=4: neighbor plane 3 at (r, w+1) -> shift stashed centers left
        float eA = (w0 + 4 < WI) ? sigf(__ldg(A + 3 * HW + off + 4)) : 0.f;
        float eD = (w0 + 4 < WI) ? sigf(__ldg(D + 3 * HW + off + 4)) : 0.f;
        float4 n1 = make_float4(pa3.y, pa3.z, pa3.w, eA);
        float4 n2 = make_float4(pd3.y, pd3.z, pd3.w, eD);
        float4 t4 = ld4(C + 4 * HW + off);
        LACC4(pa4, pd4, n1, n2, t4);
    }

    // Remaining channels: neighbor plane j=7-ch lives on row r+dr (dr=+-1).
    const int chs[6] = { 0,  1,  2,  5, 6, 7 };
    const int drs[6] = {-1, -1, -1,  1, 1, 1 };   // drt[7-ch]
    const int dws[6] = {-1,  0,  1, -1, 0, 1 };   // dwt[7-ch]
#pragma unroll
    for (int k = 0; k < 6; k++) {
        int ch = chs[k], j = 7 - ch;
        int rn = r + drs[k];
        bool rv = (unsigned)rn < (unsigned)HI;
        float4 n1 = nbr4(A + j * HW + rn * WI, rv, w0, dws[k]);
        float4 n2 = nbr4(D + j * HW + rn * WI, rv, w0, dws[k]);
        float4 pa = sig4(ld4(A + ch * HW + off));
        float4 pd = sig4(ld4(D + ch * HW + off));
        float4 t4 = ld4(C + ch * HW + off);
        LACC4(pa, pd, n1, n2, t4);
    }

    // ---- per-pixel finalize (log2 domain) ----
    const float LN2 = 0.69314718055994531f;
    float4 tg = ld4(target + (size_t)b * HW + off);
    float tga[4] = { tg.x, tg.y, tg.z, tg.w };
    float big2 = 0.f, extrasum = 0.f, small2 = 0.f;
#pragma unroll
    for (int i = 0; i < 4; i++) {
        Acc& a = ac[i];
        big2 += 0.8f * __log2f(a.prodP) + 0.2f * __log2f(a.prodV);
        extrasum += a.extra;
        float g1 = a.g1 * 0.125f;               // glo_map1
        float g2 = a.g2 * 0.125f;               // glo_map2
        bool tt = tga[i] > 0.5f;
        float sm2 = clog2f_(tt ? g1 : 1.f - g1);       // bce_loss1
        bool edge = (a.s > 0.5f) && (a.s < 7.5f);      // 0 < sum(con) < 8
        float dec = edge ? (1.f - a.vmin) : g2;        // decouple_map
        sm2 += clog2f_(tt ? dec : 1.f - dec);          // de_loss2
        small2 += sm2;
    }
    float big   = LN2 * big2 + extrasum;
    float small = LN2 * small2;

    // ---- block reduction ----
#pragma unroll
    for (int o = 16; o > 0; o >>= 1) {
        big   += __shfl_down_sync(0xffffffffu, big, o);
        small += __shfl_down_sync(0xffffffffu, small, o);
    }
    __shared__ float sb[4], ss[4];
    int lane = threadIdx.x & 31;
    int wid  = threadIdx.x >> 5;
    if (lane == 0) { sb[wid] = big; ss[wid] = small; }
    __syncthreads();
    if (wid == 0) {
        big   = (lane < 4) ? sb[lane] : 0.f;
        small = (lane < 4) ? ss[lane] : 0.f;
#pragma unroll
        for (int o = 2; o > 0; o >>= 1) {
            big   += __shfl_down_sync(0xffffffffu, big, o);
            small += __shfl_down_sync(0xffffffffu, small, o);
        }
        if (lane == 0) {
            atomicAdd(&g_big,   (double)big);
            atomicAdd(&g_small, (double)small);
            __threadfence();
            unsigned t = atomicAdd(&g_ticket, 1u);
            if (t == (unsigned)(NBLK - 1)) {
                double B = atomicAdd(&g_big,   0.0);
                double S = atomicAdd(&g_small, 0.0);
                const double N8 = (double)BN * CN * HW;
                const double N1 = (double)BN * HW;
                out[0] = (float)(-(B / N8) - (S / N1));
                g_big = 0.0;
                g_small = 0.0;
                __threadfence();
                g_ticket = 0u;
            }
        }
    }
}

extern "C" void kernel_launch(void* const* d_in, const int* in_sizes, int n_in,
                              void* d_out, int out_size) {
    const float* atts   = (const float*)d_in[0];
    const float* dets   = (const float*)d_in[1];
    const float* target = (const float*)d_in[2];
    const float* con    = (const float*)d_in[3];
    float* out = (float*)d_out;

    loss_k<<<NBLK, TPB>>>(atts, dets, target, con, out);
}

// round 9
// speedup vs baseline: 1.6977x; 1.6977x over previous
#include <cuda_runtime.h>

#define WI 512
#define HI 512
#define BN 8
#define CN 8
#define HW (HI * WI)
#define TPB 256
#define NBLK ((BN * HW) / TPB)   // 8192

// Accumulators (module-load zeroed; last block resets them each call so the
// kernel stays deterministic across graph replays).
__device__ double g_big;        // sum over B*C*H*W weighted terms
__device__ double g_small;      // sum over B*1*H*W terms (bce1 + de2)
__device__ unsigned g_ticket;   // completion ticket

// sigmoid via single MUFU.TANH: sigma(x) = 0.5*tanh(x/2) + 0.5
__device__ __forceinline__ float sigf(float x) {
    float t;
    asm("tanh.approx.f32 %0, %1;" : "=f"(t) : "f"(0.5f * x));
    return fmaf(0.5f, t, 0.5f);
}
// clamped log in log2 domain: max(log(x), -100) = ln2 * max(log2(x), -100/ln2)
#define CLOG2_MIN (-144.26950408889634f)
__device__ __forceinline__ float clog2f_(float x) {
    return fmaxf(__log2f(x), CLOG2_MIN);
}
// neighbor prob; shifts zero-pad the PROBABILITY -> OOB = exactly 0.0
__device__ __forceinline__ float nbr(const float* __restrict__ plane, int r, int w) {
    if ((unsigned)r >= (unsigned)HI || (unsigned)w >= (unsigned)WI) return 0.0f;
    return sigf(__ldg(plane + r * WI + w));
}

__global__ void __launch_bounds__(TPB) loss_k(
    const float* __restrict__ atts, const float* __restrict__ dets,
    const float* __restrict__ target, const float* __restrict__ con,
    float* __restrict__ out)
{
    int idx = blockIdx.x * TPB + threadIdx.x;   // [0, B*H*W)
    int w = idx & (WI - 1);
    int r = (idx >> 9) & (HI - 1);
    int b = idx >> 18;
    int off = r * WI + w;

    const float* A = atts + (size_t)b * CN * HW;
    const float* D = dets + (size_t)b * CN * HW;
    const float* C = con  + (size_t)b * CN * HW;

    float pa[8], pd[8], v1[8], v2[8];
#pragma unroll
    for (int ch = 0; ch < 8; ch++) {
        pa[ch] = sigf(__ldg(A + ch * HW + off));
        pd[ch] = sigf(__ldg(D + ch * HW + off));
    }
    // v[ch] = p[ch] * prob[7-ch] at offset (drt[7-ch], dwt[7-ch])
    const int drt[8] = { 1, 1, 1, 0, 0, -1, -1, -1 };
    const int dwt[8] = { 1, 0, -1, 1, -1, 1, 0, -1 };
#pragma unroll
    for (int ch = 0; ch < 8; ch++) {
        const int j = 7 - ch;
        v1[ch] = pa[ch] * nbr(A + j * HW, r + drt[j], w + dwt[j]);
        v2[ch] = pd[ch] * nbr(D + j * HW, r + drt[j], w + dwt[j]);
    }

    // Binary targets: each BCE term is one selected factor; fuse into products.
    // prodP: 16 factors in [~0.003, ~0.997] -> no under/overflow in practice.
    // prodV: vote factors are EXACTLY 0 only at zero-padded borders with t==1,
    // and then v1==0 <=> v2==0 (identical padding geometry): escape both with
    // the -100 clamp analytically (weight 0.2 each -> -40).
    float prodP = 1.0f, prodV = 1.0f, extra = 0.0f;
    float g1 = 0.0f, g2 = 0.0f, s = 0.0f, vmin = 2.0f;
#pragma unroll
    for (int ch = 0; ch < 8; ch++) {
        float t = __ldg(C + ch * HW + off);      // binary 0/1
        s += t;
        bool tt = t > 0.5f;
        float fa = tt ? pa[ch] : 1.0f - pa[ch];
        float fd = tt ? pd[ch] : 1.0f - pd[ch];
        prodP *= fa * fd;
        float f1 = tt ? v1[ch] : 1.0f - v1[ch];
        float f2 = tt ? v2[ch] : 1.0f - v2[ch];
        if (f1 == 0.0f) extra += -40.0f;         // f2 == 0 too; 2 * 0.2 * (-100)
        else            prodV *= f1 * f2;
        g1 += v1[ch]; g2 += v2[ch];
        vmin = fminf(vmin, v2[ch]);
    }

    const float LN2 = 0.69314718055994531f;
    float big = LN2 * (0.8f * __log2f(prodP) + 0.2f * __log2f(prodV)) + extra;

    g1 *= 0.125f;   // glo_map1
    g2 *= 0.125f;   // glo_map2

    float tg = __ldg(target + (size_t)b * HW + off);
    bool tt = tg > 0.5f;
    float sm2 = clog2f_(tt ? g1 : 1.0f - g1);    // bce_loss1 (log2 domain)
    bool edge = (s > 0.5f) && (s < 7.5f);        // 0 < sum(con) < 8
    float dec = edge ? (1.0f - vmin) : g2;       // decouple_map
    sm2 += clog2f_(tt ? dec : 1.0f - dec);       // de_loss2
    float small = LN2 * sm2;

    // ---- block reduction (two floats) ----
#pragma unroll
    for (int o = 16; o > 0; o >>= 1) {
        big   += __shfl_down_sync(0xffffffffu, big, o);
        small += __shfl_down_sync(0xffffffffu, small, o);
    }
    __shared__ float sb[8], ss[8];
    int lane = threadIdx.x & 31;
    int wid  = threadIdx.x >> 5;
    if (lane == 0) { sb[wid] = big; ss[wid] = small; }
    __syncthreads();
    if (wid == 0) {
        big   = (lane < 8) ? sb[lane] : 0.0f;
        small = (lane < 8) ? ss[lane] : 0.0f;
#pragma unroll
        for (int o = 4; o > 0; o >>= 1) {
            big   += __shfl_down_sync(0xffffffffu, big, o);
            small += __shfl_down_sync(0xffffffffu, small, o);
        }
        if (lane == 0) {
            atomicAdd(&g_big,   (double)big);
            atomicAdd(&g_small, (double)small);
            __threadfence();
            unsigned t = atomicAdd(&g_ticket, 1u);
            if (t == (unsigned)(NBLK - 1)) {
                // last block: finalize, write output, reset for next replay
                double B = atomicAdd(&g_big,   0.0);   // L2-coherent read
                double S = atomicAdd(&g_small, 0.0);
                const double N8 = (double)BN * CN * HW;  // 16777216
                const double N1 = (double)BN * HW;       // 2097152
                out[0] = (float)(-(B / N8) - (S / N1));
                g_big = 0.0;
                g_small = 0.0;
                __threadfence();
                g_ticket = 0u;
            }
        }
    }
}

extern "C" void kernel_launch(void* const* d_in, const int* in_sizes, int n_in,
                              void* d_out, int out_size) {
    const float* atts   = (const float*)d_in[0];
    const float* dets   = (const float*)d_in[1];
    const float* target = (const float*)d_in[2];
    const float* con    = (const float*)d_in[3];
    float* out = (float*)d_out;

    loss_k<<<NBLK, TPB>>>(atts, dets, target, con, out);
}